// round 13
// baseline (speedup 1.0000x reference)
#include <cuda_runtime.h>
#include <cuda_fp16.h>
#include <math.h>
#include <cstdint>

#define B_    2
#define T_    2048
#define NTOK  4096
#define DIM_  1024
#define HID_  4096
#define NH_   16
#define HD_   64

// Scratch (allocation-free rule: __device__ globals)
__device__ __half g_h1 [NTOK * DIM_];
__device__ __half g_qkv[NTOK * 3 * DIM_];
__device__ __half g_att[NTOK * DIM_];
__device__ float  g_x2 [NTOK * DIM_];
__device__ __half g_h2 [NTOK * DIM_];
__device__ __half g_f1 [NTOK * HID_];
// fp16 weights [K,N]
__device__ __half g_wq [DIM_ * 3 * DIM_];
__device__ __half g_wp [DIM_ * DIM_];
__device__ __half g_w1 [DIM_ * HID_];
__device__ __half g_w2 [HID_ * DIM_];

// ---------------------------------------------------------------------------
// fp32 -> fp16 conversion (weights), float2 -> half2
// ---------------------------------------------------------------------------
__global__ __launch_bounds__(256) void tohalf_kernel(
    const float* __restrict__ in, __half* __restrict__ out, int n2)
{
    int i = blockIdx.x * 256 + threadIdx.x;
    if (i < n2) {
        float2 v = ((const float2*)in)[i];
        ((__half2*)out)[i] = __floats2half2_rn(v.x, v.y);
    }
}

// ---------------------------------------------------------------------------
// LayerNorm: one block per row, 256 threads. Output fp16.
// ---------------------------------------------------------------------------
__global__ __launch_bounds__(256) void ln_kernel(
    const float* __restrict__ x, const float* __restrict__ w,
    const float* __restrict__ b, __half* __restrict__ y)
{
    int row = blockIdx.x;
    const float* xr = x + (size_t)row * DIM_;
    float s = 0.f, s2 = 0.f;
    for (int i = threadIdx.x; i < DIM_; i += 256) {
        float v = xr[i]; s += v; s2 += v * v;
    }
    __shared__ float rs[8], rs2[8];
    for (int o = 16; o; o >>= 1) {
        s  += __shfl_down_sync(0xffffffffu, s,  o);
        s2 += __shfl_down_sync(0xffffffffu, s2, o);
    }
    int wid = threadIdx.x >> 5, lane = threadIdx.x & 31;
    if (!lane) { rs[wid] = s; rs2[wid] = s2; }
    __syncthreads();
    __shared__ float mu_s, inv_s;
    if (threadIdx.x == 0) {
        float t = 0.f, t2 = 0.f;
        for (int i = 0; i < 8; i++) { t += rs[i]; t2 += rs2[i]; }
        float mu = t / (float)DIM_;
        float var = t2 / (float)DIM_ - mu * mu;
        mu_s = mu;
        inv_s = rsqrtf(var + 1e-5f);
    }
    __syncthreads();
    float mu = mu_s, inv = inv_s;
    __half* yr = y + (size_t)row * DIM_;
    for (int i = threadIdx.x; i < DIM_; i += 256)
        yr[i] = __float2half_rn((xr[i] - mu) * inv * w[i] + b[i]);
}

// ---------------------------------------------------------------------------
// FP16 HMMA GEMM v2: CTA 128x128, 128 thr (4 warps 2x2, warp tile 64x64),
// BK=32 (two m16n8k16 substeps), 4-stage cp.async ring, 2 CTAs/SM.
// Fragments for both substeps loaded before MMA burst (register dbl-buffer).
// EPI: 0 plain (half out) | 1 +bias+residual (float out) | 2 +bias+GELU (half)
// ---------------------------------------------------------------------------
__device__ __forceinline__ void mma_f16(float* c, const unsigned* a,
                                        const unsigned* b) {
    asm volatile(
        "mma.sync.aligned.m16n8k16.row.col.f32.f16.f16.f32 "
        "{%0,%1,%2,%3}, {%4,%5,%6,%7}, {%8,%9}, {%0,%1,%2,%3};"
        : "+f"(c[0]), "+f"(c[1]), "+f"(c[2]), "+f"(c[3])
        : "r"(a[0]), "r"(a[1]), "r"(a[2]), "r"(a[3]),
          "r"(b[0]), "r"(b[1]));
}

#define BM 128
#define BN 128
#define BKk 32
#define ASTRW 20              // words per A row (16 data + 4 pad)
#define BSTRW 68              // words per B row (64 data + 4 pad)
#define SAW   (BM * ASTRW)    // 2560 words
#define SBWW  (BKk * BSTRW)   // 2176 words
#define SWW   (SAW + SBWW)    // 4736 words
#define NSTAGE 4
#define GEMM_SMEM (NSTAGE * SWW * 4)   // 75776 B -> 2 CTAs/SM

#define CPASYNC16(dst, src) \
    asm volatile("cp.async.cg.shared.global [%0], [%1], 16;" \
                 :: "r"(dst), "l"(src))

template <int EPI>
__global__ __launch_bounds__(128, 2) void gemm_f16(
    const __half* __restrict__ A, const __half* __restrict__ Bm,
    const float* __restrict__ bias, const float* __restrict__ res,
    void* __restrict__ Cv, int M, int N, int K)
{
    extern __shared__ float smf[];
    unsigned sbase = (unsigned)__cvta_generic_to_shared(smf);

    int tid = threadIdx.x, lane = tid & 31, warp = tid >> 5;
    int wr = warp >> 1, wc = warp & 1;
    int row0 = blockIdx.y * BM, col0 = blockIdx.x * BN;
    int g = lane >> 2, t = lane & 3;

    const __half* Ah = A  + (size_t)row0 * K;
    const __half* Bh = Bm + col0;

    int a_lr = lane & 15, a_lc = lane >> 4;
    int b_lr = lane & 15;

    float acc[4][8][4] = {};
    int iters = K / BKk;

#define LOAD_STAGE(st, kt) do {                                            \
        unsigned sa_ = sbase + (unsigned)((st) * SWW) * 4u;                \
        unsigned sb_ = sa_ + SAW * 4u;                                     \
        int kof = (kt) * BKk;                                              \
        _Pragma("unroll")                                                  \
        for (int p = 0; p < 4; p++) {                                      \
            int id = tid + 128 * p, r = id >> 2, c = id & 3;               \
            CPASYNC16(sa_ + (unsigned)(r * ASTRW + c * 4) * 4u,            \
                      Ah + (size_t)r * K + kof + c * 8);                   \
        }                                                                  \
        _Pragma("unroll")                                                  \
        for (int p = 0; p < 4; p++) {                                      \
            int id = tid + 128 * p, r = id >> 4, c = id & 15;              \
            CPASYNC16(sb_ + (unsigned)(r * BSTRW + c * 4) * 4u,            \
                      Bh + (size_t)(kof + r) * N + c * 8);                 \
        }                                                                  \
    } while (0)

#pragma unroll
    for (int s = 0; s < NSTAGE - 1; s++) {
        LOAD_STAGE(s, s);
        asm volatile("cp.async.commit_group;");
    }

    for (int it = 0; it < iters; it++) {
        asm volatile("cp.async.wait_group %0;" :: "n"(NSTAGE - 2));
        __syncthreads();

        int nk = it + NSTAGE - 1;
        if (nk < iters) LOAD_STAGE(nk % NSTAGE, nk);
        asm volatile("cp.async.commit_group;");

        unsigned sa = sbase + (unsigned)((it % NSTAGE) * SWW) * 4u;
        unsigned sb = sa + SAW * 4u;

        unsigned af[2][4][4], bf[2][8][2];
#pragma unroll
        for (int ks = 0; ks < 2; ks++) {
#pragma unroll
            for (int mt = 0; mt < 4; mt++) {
                unsigned ad = sa + (unsigned)(
                    (wr * 64 + mt * 16 + a_lr) * ASTRW
                    + ks * 8 + a_lc * 4) * 4u;
                asm volatile(
                    "ldmatrix.sync.aligned.m8n8.x4.shared.b16 "
                    "{%0,%1,%2,%3}, [%4];"
                    : "=r"(af[ks][mt][0]), "=r"(af[ks][mt][1]),
                      "=r"(af[ks][mt][2]), "=r"(af[ks][mt][3])
                    : "r"(ad));
            }
#pragma unroll
            for (int nt = 0; nt < 8; nt++) {
                unsigned bd = sb + (unsigned)((ks * 16 + b_lr) * BSTRW) * 4u
                            + (unsigned)((wc * 64 + nt * 8) * 2);
                asm volatile(
                    "ldmatrix.sync.aligned.m8n8.x2.trans.shared.b16 "
                    "{%0,%1}, [%2];"
                    : "=r"(bf[ks][nt][0]), "=r"(bf[ks][nt][1])
                    : "r"(bd));
            }
        }
#pragma unroll
        for (int ks = 0; ks < 2; ks++)
#pragma unroll
            for (int mt = 0; mt < 4; mt++)
#pragma unroll
                for (int nt = 0; nt < 8; nt++)
                    mma_f16(acc[mt][nt], af[ks][mt], bf[ks][nt]);
    }
#undef LOAD_STAGE

#pragma unroll
    for (int mt = 0; mt < 4; mt++) {
#pragma unroll
        for (int nt = 0; nt < 8; nt++) {
            int r = row0 + wr * 64 + mt * 16 + g;
            int c = col0 + wc * 64 + nt * 8 + t * 2;
#pragma unroll
            for (int half = 0; half < 2; half++) {
                int rr = r + half * 8;
                float v0 = acc[mt][nt][half * 2 + 0];
                float v1 = acc[mt][nt][half * 2 + 1];
                if (EPI == 0) {
                    __half* Ch = (__half*)Cv;
                    *(__half2*)(Ch + (size_t)rr * N + c) =
                        __floats2half2_rn(v0, v1);
                } else if (EPI == 2) {
                    v0 += bias[c];
                    v1 += bias[c + 1];
                    v0 = 0.5f * v0 * (1.f + erff(v0 * 0.70710678118654752f));
                    v1 = 0.5f * v1 * (1.f + erff(v1 * 0.70710678118654752f));
                    __half* Ch = (__half*)Cv;
                    *(__half2*)(Ch + (size_t)rr * N + c) =
                        __floats2half2_rn(v0, v1);
                } else {
                    const float* rp = res + (size_t)rr * N + c;
                    v0 += bias[c]     + rp[0];
                    v1 += bias[c + 1] + rp[1];
                    float* Cf = (float*)Cv;
                    *(float2*)(Cf + (size_t)rr * N + c) = make_float2(v0, v1);
                }
            }
        }
    }
}

// ---------------------------------------------------------------------------
// FP16 tensor-core flash attention (R12), causal + key-padding. 2 CTAs/SM.
// ---------------------------------------------------------------------------
#define QT 128
#define KT 64
#define HSTR 72   // halves per smem row (64 + 8 pad)
#define ATTN_SMEM ((QT + KT + KT) * HSTR * 2 + KT * 4)

__global__ __launch_bounds__(128, 2) void attn_f16(
    const __half* __restrict__ qkv, const int* __restrict__ kpm,
    __half* __restrict__ out)
{
    extern __shared__ __align__(16) char smraw[];
    __half* Qs = (__half*)smraw;                 // [128][72]
    __half* Kt = Qs + QT * HSTR;                 // [64 d][72 tok]
    __half* Vs = Kt + KT * HSTR;                 // [64 tok][72 d]
    float* padv = (float*)(Vs + KT * HSTR);      // [64]
    unsigned sbase = (unsigned)__cvta_generic_to_shared(smraw);

    int qb = blockIdx.x, h = blockIdx.y, b = blockIdx.z;
    int tid = threadIdx.x, lane = tid & 31, warp = tid >> 5;
    int g = lane >> 2, t = lane & 3;
    const int lds = 3 * DIM_;
    const float scale = 0.125f;

    size_t qbase = ((size_t)(b * T_ + qb * QT)) * lds + h * HD_;
    for (int idx = tid; idx < QT * 8; idx += 128) {
        int r = idx >> 3, c8 = (idx & 7) * 8;
        uint4 v = *(const uint4*)(qkv + qbase + (size_t)r * lds + c8);
        __half2* hp = (__half2*)&v;
#pragma unroll
        for (int i = 0; i < 4; i++) {
            float2 f = __half22float2(hp[i]);
            hp[i] = __floats2half2_rn(f.x * scale, f.y * scale);
        }
        *(uint4*)(Qs + r * HSTR + c8) = v;
    }
    __syncthreads();

    int a_lr = lane & 15, a_lc = lane >> 4;
    unsigned qf[2][4][4];
#pragma unroll
    for (int mt = 0; mt < 2; mt++)
#pragma unroll
        for (int ks = 0; ks < 4; ks++) {
            unsigned ad = sbase + (unsigned)(
                (warp * 32 + mt * 16 + a_lr) * HSTR + ks * 16 + a_lc * 8) * 2u;
            asm volatile(
                "ldmatrix.sync.aligned.m8n8.x4.shared.b16 {%0,%1,%2,%3}, [%4];"
                : "=r"(qf[mt][ks][0]), "=r"(qf[mt][ks][1]),
                  "=r"(qf[mt][ks][2]), "=r"(qf[mt][ks][3])
                : "r"(ad));
        }

    unsigned ktbase = sbase + (unsigned)(QT * HSTR) * 2u;
    unsigned vsbase = ktbase + (unsigned)(KT * HSTR) * 2u;
    int b_lr = lane & 15;

    float m[2][2], l[2][2], o[2][8][4];
#pragma unroll
    for (int mt = 0; mt < 2; mt++)
#pragma unroll
        for (int hf = 0; hf < 2; hf++) { m[mt][hf] = -1e30f; l[mt][hf] = 0.f; }
#pragma unroll
    for (int mt = 0; mt < 2; mt++)
#pragma unroll
        for (int nt = 0; nt < 8; nt++)
#pragma unroll
            for (int i = 0; i < 4; i++) o[mt][nt][i] = 0.f;

    int ktiles = 2 * qb + 2;
    for (int kt = 0; kt < ktiles; kt++) {
        __syncthreads();
        size_t kbase = ((size_t)(b * T_ + kt * KT)) * lds + DIM_ + h * HD_;
        size_t vbase = kbase + DIM_;
        for (int idx = tid; idx < KT * 8; idx += 128) {
            int tok = idx & 63, d8 = (idx >> 6) * 8;
            uint4 v = *(const uint4*)(qkv + kbase + (size_t)tok * lds + d8);
            const __half* hp = (const __half*)&v;
#pragma unroll
            for (int i = 0; i < 8; i++)
                Kt[(d8 + i) * HSTR + tok] = hp[i];
        }
        for (int idx = tid; idx < KT * 8; idx += 128) {
            int tok = idx >> 3, d8 = (idx & 7) * 8;
            uint4 v = *(const uint4*)(qkv + vbase + (size_t)tok * lds + d8);
            *(uint4*)(Vs + tok * HSTR + d8) = v;
        }
        if (tid < KT)
            padv[tid] = kpm[b * T_ + kt * KT + tid] ? -1e9f : 0.f;
        __syncthreads();

        float s[2][8][4];
#pragma unroll
        for (int mt = 0; mt < 2; mt++)
#pragma unroll
            for (int nt = 0; nt < 8; nt++)
#pragma unroll
                for (int i = 0; i < 4; i++) s[mt][nt][i] = 0.f;

#pragma unroll
        for (int ks = 0; ks < 4; ks++) {
            unsigned bf[8][2];
#pragma unroll
            for (int nt = 0; nt < 8; nt++) {
                unsigned bd = ktbase +
                    (unsigned)((ks * 16 + b_lr) * HSTR + nt * 8) * 2u;
                asm volatile(
                    "ldmatrix.sync.aligned.m8n8.x2.trans.shared.b16 "
                    "{%0,%1}, [%2];"
                    : "=r"(bf[nt][0]), "=r"(bf[nt][1]) : "r"(bd));
            }
#pragma unroll
            for (int mt = 0; mt < 2; mt++)
#pragma unroll
                for (int nt = 0; nt < 8; nt++)
                    mma_f16(s[mt][nt], qf[mt][ks], bf[nt]);
        }

        float pv0[8], pv1[8];
#pragma unroll
        for (int nt = 0; nt < 8; nt++) {
            pv0[nt] = padv[nt * 8 + t * 2];
            pv1[nt] = padv[nt * 8 + t * 2 + 1];
        }
        bool dodiag = (kt >= 2 * qb);
#pragma unroll
        for (int mt = 0; mt < 2; mt++) {
#pragma unroll
            for (int hf = 0; hf < 2; hf++) {
                int rloc = warp * 32 + mt * 16 + g + hf * 8;
                int rglob = qb * QT + rloc;
                float tmax = -1e30f;
#pragma unroll
                for (int nt = 0; nt < 8; nt++) {
                    float v0 = s[mt][nt][hf * 2]     + pv0[nt];
                    float v1 = s[mt][nt][hf * 2 + 1] + pv1[nt];
                    if (dodiag) {
                        int c0 = kt * KT + nt * 8 + t * 2;
                        if (c0     > rglob) v0 = -1e30f;
                        if (c0 + 1 > rglob) v1 = -1e30f;
                    }
                    s[mt][nt][hf * 2]     = v0;
                    s[mt][nt][hf * 2 + 1] = v1;
                    tmax = fmaxf(tmax, fmaxf(v0, v1));
                }
                tmax = fmaxf(tmax, __shfl_xor_sync(0xffffffffu, tmax, 1));
                tmax = fmaxf(tmax, __shfl_xor_sync(0xffffffffu, tmax, 2));
                float mold = m[mt][hf];
                float mnew = fmaxf(mold, tmax);
                float al = __expf(mold - mnew);
                float rsum = 0.f;
#pragma unroll
                for (int nt = 0; nt < 8; nt++) {
                    float p0 = __expf(s[mt][nt][hf * 2]     - mnew);
                    float p1 = __expf(s[mt][nt][hf * 2 + 1] - mnew);
                    rsum += p0 + p1;
                    s[mt][nt][hf * 2]     = p0;
                    s[mt][nt][hf * 2 + 1] = p1;
                }
                rsum += __shfl_xor_sync(0xffffffffu, rsum, 1);
                rsum += __shfl_xor_sync(0xffffffffu, rsum, 2);
                m[mt][hf] = mnew;
                l[mt][hf] = l[mt][hf] * al + rsum;
#pragma unroll
                for (int nt = 0; nt < 8; nt++) {
                    o[mt][nt][hf * 2]     *= al;
                    o[mt][nt][hf * 2 + 1] *= al;
                }
            }
        }

        unsigned pf[2][4][4];
#pragma unroll
        for (int mt = 0; mt < 2; mt++)
#pragma unroll
            for (int j = 0; j < 4; j++) {
                __half2 h0 = __floats2half2_rn(s[mt][2*j][0],   s[mt][2*j][1]);
                __half2 h1 = __floats2half2_rn(s[mt][2*j][2],   s[mt][2*j][3]);
                __half2 h2 = __floats2half2_rn(s[mt][2*j+1][0], s[mt][2*j+1][1]);
                __half2 h3 = __floats2half2_rn(s[mt][2*j+1][2], s[mt][2*j+1][3]);
                pf[mt][j][0] = *(unsigned*)&h0;
                pf[mt][j][1] = *(unsigned*)&h1;
                pf[mt][j][2] = *(unsigned*)&h2;
                pf[mt][j][3] = *(unsigned*)&h3;
            }

#pragma unroll
        for (int j = 0; j < 4; j++) {
            unsigned bf[8][2];
#pragma unroll
            for (int nt = 0; nt < 8; nt++) {
                unsigned bd = vsbase +
                    (unsigned)((j * 16 + b_lr) * HSTR + nt * 8) * 2u;
                asm volatile(
                    "ldmatrix.sync.aligned.m8n8.x2.trans.shared.b16 "
                    "{%0,%1}, [%2];"
                    : "=r"(bf[nt][0]), "=r"(bf[nt][1]) : "r"(bd));
            }
#pragma unroll
            for (int mt = 0; mt < 2; mt++)
#pragma unroll
                for (int nt = 0; nt < 8; nt++)
                    mma_f16(o[mt][nt], pf[mt][j], bf[nt]);
        }
    }

#pragma unroll
    for (int mt = 0; mt < 2; mt++) {
#pragma unroll
        for (int hf = 0; hf < 2; hf++) {
            int rloc = warp * 32 + mt * 16 + g + hf * 8;
            float invl = 1.f / l[mt][hf];
            size_t ob = ((size_t)(b * T_ + qb * QT + rloc)) * DIM_ + h * HD_;
#pragma unroll
            for (int nt = 0; nt < 8; nt++) {
                int c = nt * 8 + t * 2;
                *(__half2*)(out + ob + c) = __floats2half2_rn(
                    o[mt][nt][hf * 2]     * invl,
                    o[mt][nt][hf * 2 + 1] * invl);
            }
        }
    }
}

// ---------------------------------------------------------------------------
extern "C" void kernel_launch(void* const* d_in, const int* in_sizes, int n_in,
                              void* d_out, int out_size)
{
    const float* x     = (const float*)d_in[0];
    const int*   kpm   = (const int*)  d_in[1];
    const float* ln1w  = (const float*)d_in[2];
    const float* ln1b  = (const float*)d_in[3];
    const float* qkvw  = (const float*)d_in[4];
    const float* projw = (const float*)d_in[5];
    const float* projb = (const float*)d_in[6];
    const float* ln2w  = (const float*)d_in[7];
    const float* ln2b  = (const float*)d_in[8];
    const float* fc1w  = (const float*)d_in[9];
    const float* fc1b  = (const float*)d_in[10];
    const float* fc2w  = (const float*)d_in[11];
    const float* fc2b  = (const float*)d_in[12];
    float* out = (float*)d_out;

    __half *h1, *qkv, *att, *h2, *f1, *wq, *wp, *w1, *w2;
    float *x2;
    cudaGetSymbolAddress((void**)&h1,  g_h1);
    cudaGetSymbolAddress((void**)&qkv, g_qkv);
    cudaGetSymbolAddress((void**)&att, g_att);
    cudaGetSymbolAddress((void**)&x2,  g_x2);
    cudaGetSymbolAddress((void**)&h2,  g_h2);
    cudaGetSymbolAddress((void**)&f1,  g_f1);
    cudaGetSymbolAddress((void**)&wq,  g_wq);
    cudaGetSymbolAddress((void**)&wp,  g_wp);
    cudaGetSymbolAddress((void**)&w1,  g_w1);
    cudaGetSymbolAddress((void**)&w2,  g_w2);

    cudaFuncSetAttribute(attn_f16,
        cudaFuncAttributeMaxDynamicSharedMemorySize, ATTN_SMEM);
    cudaFuncSetAttribute(gemm_f16<0>,
        cudaFuncAttributeMaxDynamicSharedMemorySize, GEMM_SMEM);
    cudaFuncSetAttribute(gemm_f16<1>,
        cudaFuncAttributeMaxDynamicSharedMemorySize, GEMM_SMEM);
    cudaFuncSetAttribute(gemm_f16<2>,
        cudaFuncAttributeMaxDynamicSharedMemorySize, GEMM_SMEM);

    // 0) convert weights to fp16
    tohalf_kernel<<<(DIM_*3*DIM_/2 + 255)/256, 256>>>(qkvw, wq, DIM_*3*DIM_/2);
    tohalf_kernel<<<(DIM_*DIM_/2   + 255)/256, 256>>>(projw, wp, DIM_*DIM_/2);
    tohalf_kernel<<<(DIM_*HID_/2   + 255)/256, 256>>>(fc1w,  w1, DIM_*HID_/2);
    tohalf_kernel<<<(HID_*DIM_/2   + 255)/256, 256>>>(fc2w,  w2, HID_*DIM_/2);

    // 1) LN1 (fp16 out)
    ln_kernel<<<NTOK, 256>>>(x, ln1w, ln1b, h1);
    // 2) QKV GEMM (fp16 out)
    gemm_f16<0><<<dim3(3*DIM_/BN, NTOK/BM), 128, GEMM_SMEM>>>(
        h1, wq, nullptr, nullptr, qkv, NTOK, 3*DIM_, DIM_);
    // 3) Attention (fp16 in/out)
    attn_f16<<<dim3(T_/QT, NH_, B_), 128, ATTN_SMEM>>>(qkv, kpm, att);
    // 4) proj GEMM + bias + residual(x) -> x2 (float)
    gemm_f16<1><<<dim3(DIM_/BN, NTOK/BM), 128, GEMM_SMEM>>>(
        att, wp, projb, x, x2, NTOK, DIM_, DIM_);
    // 5) LN2 (fp16 out)
    ln_kernel<<<NTOK, 256>>>(x2, ln2w, ln2b, h2);
    // 6) fc1 GEMM + bias + GELU -> f1 (fp16)
    gemm_f16<2><<<dim3(HID_/BN, NTOK/BM), 128, GEMM_SMEM>>>(
        h2, w1, fc1b, nullptr, f1, NTOK, HID_, DIM_);
    // 7) fc2 GEMM + bias + residual(x2) -> out (float)
    gemm_f16<1><<<dim3(DIM_/BN, NTOK/BM), 128, GEMM_SMEM>>>(
        f1, w2, fc2b, x2, out, NTOK, DIM_, HID_);
}

// round 14
// speedup vs baseline: 1.0435x; 1.0435x over previous
#include <cuda_runtime.h>
#include <cuda_fp16.h>
#include <math.h>
#include <cstdint>

#define B_    2
#define T_    2048
#define NTOK  4096
#define DIM_  1024
#define HID_  4096
#define NH_   16
#define HD_   64

// Scratch (allocation-free rule: __device__ globals)
__device__ __half g_h1 [NTOK * DIM_];
__device__ __half g_qkv[NTOK * 3 * DIM_];
__device__ __half g_att[NTOK * DIM_];
__device__ float  g_x2 [NTOK * DIM_];
__device__ __half g_h2 [NTOK * DIM_];
__device__ __half g_f1 [NTOK * HID_];
// fp16 weights [K,N]
__device__ __half g_wq [DIM_ * 3 * DIM_];
__device__ __half g_wp [DIM_ * DIM_];
__device__ __half g_w1 [DIM_ * HID_];
__device__ __half g_w2 [HID_ * DIM_];

// ---------------------------------------------------------------------------
// LayerNorm body (device helper): one block per row, 256 threads, fp16 out.
// ---------------------------------------------------------------------------
__device__ __forceinline__ void ln_row(
    const float* __restrict__ x, const float* __restrict__ w,
    const float* __restrict__ b, __half* __restrict__ y, int row)
{
    const float* xr = x + (size_t)row * DIM_;
    float s = 0.f, s2 = 0.f;
    for (int i = threadIdx.x; i < DIM_; i += 256) {
        float v = xr[i]; s += v; s2 += v * v;
    }
    __shared__ float rs[8], rs2[8];
    for (int o = 16; o; o >>= 1) {
        s  += __shfl_down_sync(0xffffffffu, s,  o);
        s2 += __shfl_down_sync(0xffffffffu, s2, o);
    }
    int wid = threadIdx.x >> 5, lane = threadIdx.x & 31;
    if (!lane) { rs[wid] = s; rs2[wid] = s2; }
    __syncthreads();
    __shared__ float mu_s, inv_s;
    if (threadIdx.x == 0) {
        float t = 0.f, t2 = 0.f;
        for (int i = 0; i < 8; i++) { t += rs[i]; t2 += rs2[i]; }
        float mu = t / (float)DIM_;
        float var = t2 / (float)DIM_ - mu * mu;
        mu_s = mu;
        inv_s = rsqrtf(var + 1e-5f);
    }
    __syncthreads();
    float mu = mu_s, inv = inv_s;
    __half* yr = y + (size_t)row * DIM_;
    for (int i = threadIdx.x; i < DIM_; i += 256)
        yr[i] = __float2half_rn((xr[i] - mu) * inv * w[i] + b[i]);
}

__global__ __launch_bounds__(256) void ln_kernel(
    const float* __restrict__ x, const float* __restrict__ w,
    const float* __restrict__ b, __half* __restrict__ y)
{
    ln_row(x, w, b, y, blockIdx.x);
}

// ---------------------------------------------------------------------------
// Fused prologue: blocks [0, NTOK) = LN1 rows; blocks [NTOK, NTOK+3072) =
// fp32->fp16 weight conversion over the 4 concatenated weight regions.
// ---------------------------------------------------------------------------
#define CONV_BLOCKS 3072
#define CONV_PER_BLK 2048   // half2 per block (256 thr x 8)

__global__ __launch_bounds__(256) void prep_kernel(
    const float* __restrict__ x, const float* __restrict__ ln1w,
    const float* __restrict__ ln1b, __half* __restrict__ h1,
    const float* __restrict__ qkvw, const float* __restrict__ projw,
    const float* __restrict__ fc1w, const float* __restrict__ fc2w,
    __half* __restrict__ wq, __half* __restrict__ wp,
    __half* __restrict__ w1, __half* __restrict__ w2)
{
    if (blockIdx.x < NTOK) {
        ln_row(x, ln1w, ln1b, h1, blockIdx.x);
        return;
    }
    long cb = blockIdx.x - NTOK;
    const long S0 = (long)DIM_ * 3 * DIM_ / 2;
    const long S1 = S0 + (long)DIM_ * DIM_ / 2;
    const long S2 = S1 + (long)DIM_ * HID_ / 2;
#pragma unroll
    for (int i = 0; i < 8; i++) {
        long idx = cb * CONV_PER_BLK + i * 256 + threadIdx.x;
        const float* in; __half* out; long off;
        if (idx < S0)      { in = qkvw;  out = wq; off = idx; }
        else if (idx < S1) { in = projw; out = wp; off = idx - S0; }
        else if (idx < S2) { in = fc1w;  out = w1; off = idx - S1; }
        else               { in = fc2w;  out = w2; off = idx - S2; }
        float2 v = ((const float2*)in)[off];
        ((__half2*)out)[off] = __floats2half2_rn(v.x, v.y);
    }
}

// ---------------------------------------------------------------------------
// FP16 HMMA GEMM (R12): CTA 128x128, 128 thr, warp tile 64x64, 6-stage ring.
// EPI: 0 plain (half out) | 1 +bias+residual (float out) | 2 +bias+GELU (half)
// ---------------------------------------------------------------------------
__device__ __forceinline__ void mma_f16(float* c, const unsigned* a,
                                        const unsigned* b) {
    asm volatile(
        "mma.sync.aligned.m16n8k16.row.col.f32.f16.f16.f32 "
        "{%0,%1,%2,%3}, {%4,%5,%6,%7}, {%8,%9}, {%0,%1,%2,%3};"
        : "+f"(c[0]), "+f"(c[1]), "+f"(c[2]), "+f"(c[3])
        : "r"(a[0]), "r"(a[1]), "r"(a[2]), "r"(a[3]),
          "r"(b[0]), "r"(b[1]));
}

#define BM 128
#define BN 128
#define BKk 16
#define ASTRW 12
#define BSTRW 68
#define SAW   (BM * ASTRW)
#define SBWW  (BKk * BSTRW)
#define SWW   (SAW + SBWW)
#define NSTAGE 6
#define GEMM_SMEM (NSTAGE * SWW * 4)

#define CPASYNC16(dst, src) \
    asm volatile("cp.async.cg.shared.global [%0], [%1], 16;" \
                 :: "r"(dst), "l"(src))

template <int EPI>
__global__ __launch_bounds__(128, 2) void gemm_f16(
    const __half* __restrict__ A, const __half* __restrict__ Bm,
    const float* __restrict__ bias, const float* __restrict__ res,
    void* __restrict__ Cv, int M, int N, int K)
{
    extern __shared__ float smf[];
    unsigned sbase = (unsigned)__cvta_generic_to_shared(smf);

    int tid = threadIdx.x, lane = tid & 31, warp = tid >> 5;
    int wr = warp >> 1, wc = warp & 1;
    int row0 = blockIdx.y * BM, col0 = blockIdx.x * BN;
    int g = lane >> 2, t = lane & 3;

    const __half* Ah = A  + (size_t)row0 * K;
    const __half* Bh = Bm + col0;

    int a_lr = lane & 15, a_lc = lane >> 4;
    int b_lr = lane & 15;

    float acc[4][8][4] = {};
    int iters = K / BKk;

#define LOAD_STAGE(st, kt) do {                                            \
        unsigned sa_ = sbase + (unsigned)((st) * SWW) * 4u;                \
        unsigned sb_ = sa_ + SAW * 4u;                                     \
        int kof = (kt) * BKk;                                              \
        _Pragma("unroll")                                                  \
        for (int p = 0; p < 2; p++) {                                      \
            int r = (tid >> 1) + 64 * p, c = tid & 1;                      \
            CPASYNC16(sa_ + (unsigned)(r * ASTRW + c * 4) * 4u,            \
                      Ah + (size_t)r * K + kof + c * 8);                   \
        }                                                                  \
        _Pragma("unroll")                                                  \
        for (int p = 0; p < 2; p++) {                                      \
            int r = (tid >> 4) + 8 * p, c = tid & 15;                      \
            CPASYNC16(sb_ + (unsigned)(r * BSTRW + c * 4) * 4u,            \
                      Bh + (size_t)(kof + r) * N + c * 8);                 \
        }                                                                  \
    } while (0)

#pragma unroll
    for (int s = 0; s < NSTAGE - 1; s++) {
        LOAD_STAGE(s, s);
        asm volatile("cp.async.commit_group;");
    }

    for (int it = 0; it < iters; it++) {
        asm volatile("cp.async.wait_group %0;" :: "n"(NSTAGE - 2));
        __syncthreads();

        int nk = it + NSTAGE - 1;
        if (nk < iters) LOAD_STAGE(nk % NSTAGE, nk);
        asm volatile("cp.async.commit_group;");

        unsigned sa = sbase + (unsigned)((it % NSTAGE) * SWW) * 4u;
        unsigned sb = sa + SAW * 4u;

        unsigned af[4][4], bf[8][2];
#pragma unroll
        for (int mt = 0; mt < 4; mt++) {
            unsigned ad = sa +
                (unsigned)((wr * 64 + mt * 16 + a_lr) * ASTRW + a_lc * 4) * 4u;
            asm volatile(
                "ldmatrix.sync.aligned.m8n8.x4.shared.b16 {%0,%1,%2,%3}, [%4];"
                : "=r"(af[mt][0]), "=r"(af[mt][1]),
                  "=r"(af[mt][2]), "=r"(af[mt][3])
                : "r"(ad));
        }
#pragma unroll
        for (int nt = 0; nt < 8; nt++) {
            unsigned bd = sb + (unsigned)(b_lr * BSTRW) * 4u
                        + (unsigned)((wc * 64 + nt * 8) * 2);
            asm volatile(
                "ldmatrix.sync.aligned.m8n8.x2.trans.shared.b16 {%0,%1}, [%2];"
                : "=r"(bf[nt][0]), "=r"(bf[nt][1])
                : "r"(bd));
        }
#pragma unroll
        for (int mt = 0; mt < 4; mt++)
#pragma unroll
            for (int nt = 0; nt < 8; nt++)
                mma_f16(acc[mt][nt], af[mt], bf[nt]);
    }
#undef LOAD_STAGE

#pragma unroll
    for (int mt = 0; mt < 4; mt++) {
#pragma unroll
        for (int nt = 0; nt < 8; nt++) {
            int r = row0 + wr * 64 + mt * 16 + g;
            int c = col0 + wc * 64 + nt * 8 + t * 2;
#pragma unroll
            for (int half = 0; half < 2; half++) {
                int rr = r + half * 8;
                float v0 = acc[mt][nt][half * 2 + 0];
                float v1 = acc[mt][nt][half * 2 + 1];
                if (EPI == 0) {
                    __half* Ch = (__half*)Cv;
                    *(__half2*)(Ch + (size_t)rr * N + c) =
                        __floats2half2_rn(v0, v1);
                } else if (EPI == 2) {
                    v0 += bias[c];
                    v1 += bias[c + 1];
                    v0 = 0.5f * v0 * (1.f + erff(v0 * 0.70710678118654752f));
                    v1 = 0.5f * v1 * (1.f + erff(v1 * 0.70710678118654752f));
                    __half* Ch = (__half*)Cv;
                    *(__half2*)(Ch + (size_t)rr * N + c) =
                        __floats2half2_rn(v0, v1);
                } else {
                    const float* rp = res + (size_t)rr * N + c;
                    v0 += bias[c]     + rp[0];
                    v1 += bias[c + 1] + rp[1];
                    float* Cf = (float*)Cv;
                    *(float2*)(Cf + (size_t)rr * N + c) = make_float2(v0, v1);
                }
            }
        }
    }
}

// ---------------------------------------------------------------------------
// FP16 tensor-core flash attention (R12), causal + key-padding. 2 CTAs/SM.
// ---------------------------------------------------------------------------
#define QT 128
#define KT 64
#define HSTR 72   // halves per smem row (64 + 8 pad)
#define ATTN_SMEM ((QT + KT + KT) * HSTR * 2 + KT * 4)

__global__ __launch_bounds__(128, 2) void attn_f16(
    const __half* __restrict__ qkv, const int* __restrict__ kpm,
    __half* __restrict__ out)
{
    extern __shared__ __align__(16) char smraw[];
    __half* Qs = (__half*)smraw;
    __half* Kt = Qs + QT * HSTR;
    __half* Vs = Kt + KT * HSTR;
    float* padv = (float*)(Vs + KT * HSTR);
    unsigned sbase = (unsigned)__cvta_generic_to_shared(smraw);

    int qb = blockIdx.x, h = blockIdx.y, b = blockIdx.z;
    int tid = threadIdx.x, lane = tid & 31, warp = tid >> 5;
    int g = lane >> 2, t = lane & 3;
    const int lds = 3 * DIM_;
    const float scale = 0.125f;

    size_t qbase = ((size_t)(b * T_ + qb * QT)) * lds + h * HD_;
    for (int idx = tid; idx < QT * 8; idx += 128) {
        int r = idx >> 3, c8 = (idx & 7) * 8;
        uint4 v = *(const uint4*)(qkv + qbase + (size_t)r * lds + c8);
        __half2* hp = (__half2*)&v;
#pragma unroll
        for (int i = 0; i < 4; i++) {
            float2 f = __half22float2(hp[i]);
            hp[i] = __floats2half2_rn(f.x * scale, f.y * scale);
        }
        *(uint4*)(Qs + r * HSTR + c8) = v;
    }
    __syncthreads();

    int a_lr = lane & 15, a_lc = lane >> 4;
    unsigned qf[2][4][4];
#pragma unroll
    for (int mt = 0; mt < 2; mt++)
#pragma unroll
        for (int ks = 0; ks < 4; ks++) {
            unsigned ad = sbase + (unsigned)(
                (warp * 32 + mt * 16 + a_lr) * HSTR + ks * 16 + a_lc * 8) * 2u;
            asm volatile(
                "ldmatrix.sync.aligned.m8n8.x4.shared.b16 {%0,%1,%2,%3}, [%4];"
                : "=r"(qf[mt][ks][0]), "=r"(qf[mt][ks][1]),
                  "=r"(qf[mt][ks][2]), "=r"(qf[mt][ks][3])
                : "r"(ad));
        }

    unsigned ktbase = sbase + (unsigned)(QT * HSTR) * 2u;
    unsigned vsbase = ktbase + (unsigned)(KT * HSTR) * 2u;
    int b_lr = lane & 15;

    float m[2][2], l[2][2], o[2][8][4];
#pragma unroll
    for (int mt = 0; mt < 2; mt++)
#pragma unroll
        for (int hf = 0; hf < 2; hf++) { m[mt][hf] = -1e30f; l[mt][hf] = 0.f; }
#pragma unroll
    for (int mt = 0; mt < 2; mt++)
#pragma unroll
        for (int nt = 0; nt < 8; nt++)
#pragma unroll
            for (int i = 0; i < 4; i++) o[mt][nt][i] = 0.f;

    int ktiles = 2 * qb + 2;
    for (int kt = 0; kt < ktiles; kt++) {
        __syncthreads();
        size_t kbase = ((size_t)(b * T_ + kt * KT)) * lds + DIM_ + h * HD_;
        size_t vbase = kbase + DIM_;
        for (int idx = tid; idx < KT * 8; idx += 128) {
            int tok = idx & 63, d8 = (idx >> 6) * 8;
            uint4 v = *(const uint4*)(qkv + kbase + (size_t)tok * lds + d8);
            const __half* hp = (const __half*)&v;
#pragma unroll
            for (int i = 0; i < 8; i++)
                Kt[(d8 + i) * HSTR + tok] = hp[i];
        }
        for (int idx = tid; idx < KT * 8; idx += 128) {
            int tok = idx >> 3, d8 = (idx & 7) * 8;
            uint4 v = *(const uint4*)(qkv + vbase + (size_t)tok * lds + d8);
            *(uint4*)(Vs + tok * HSTR + d8) = v;
        }
        if (tid < KT)
            padv[tid] = kpm[b * T_ + kt * KT + tid] ? -1e9f : 0.f;
        __syncthreads();

        float s[2][8][4];
#pragma unroll
        for (int mt = 0; mt < 2; mt++)
#pragma unroll
            for (int nt = 0; nt < 8; nt++)
#pragma unroll
                for (int i = 0; i < 4; i++) s[mt][nt][i] = 0.f;

#pragma unroll
        for (int ks = 0; ks < 4; ks++) {
            unsigned bf[8][2];
#pragma unroll
            for (int nt = 0; nt < 8; nt++) {
                unsigned bd = ktbase +
                    (unsigned)((ks * 16 + b_lr) * HSTR + nt * 8) * 2u;
                asm volatile(
                    "ldmatrix.sync.aligned.m8n8.x2.trans.shared.b16 "
                    "{%0,%1}, [%2];"
                    : "=r"(bf[nt][0]), "=r"(bf[nt][1]) : "r"(bd));
            }
#pragma unroll
            for (int mt = 0; mt < 2; mt++)
#pragma unroll
                for (int nt = 0; nt < 8; nt++)
                    mma_f16(s[mt][nt], qf[mt][ks], bf[nt]);
        }

        float pv0[8], pv1[8];
#pragma unroll
        for (int nt = 0; nt < 8; nt++) {
            pv0[nt] = padv[nt * 8 + t * 2];
            pv1[nt] = padv[nt * 8 + t * 2 + 1];
        }
        bool dodiag = (kt >= 2 * qb);
#pragma unroll
        for (int mt = 0; mt < 2; mt++) {
#pragma unroll
            for (int hf = 0; hf < 2; hf++) {
                int rloc = warp * 32 + mt * 16 + g + hf * 8;
                int rglob = qb * QT + rloc;
                float tmax = -1e30f;
#pragma unroll
                for (int nt = 0; nt < 8; nt++) {
                    float v0 = s[mt][nt][hf * 2]     + pv0[nt];
                    float v1 = s[mt][nt][hf * 2 + 1] + pv1[nt];
                    if (dodiag) {
                        int c0 = kt * KT + nt * 8 + t * 2;
                        if (c0     > rglob) v0 = -1e30f;
                        if (c0 + 1 > rglob) v1 = -1e30f;
                    }
                    s[mt][nt][hf * 2]     = v0;
                    s[mt][nt][hf * 2 + 1] = v1;
                    tmax = fmaxf(tmax, fmaxf(v0, v1));
                }
                tmax = fmaxf(tmax, __shfl_xor_sync(0xffffffffu, tmax, 1));
                tmax = fmaxf(tmax, __shfl_xor_sync(0xffffffffu, tmax, 2));
                float mold = m[mt][hf];
                float mnew = fmaxf(mold, tmax);
                float al = __expf(mold - mnew);
                float rsum = 0.f;
#pragma unroll
                for (int nt = 0; nt < 8; nt++) {
                    float p0 = __expf(s[mt][nt][hf * 2]     - mnew);
                    float p1 = __expf(s[mt][nt][hf * 2 + 1] - mnew);
                    rsum += p0 + p1;
                    s[mt][nt][hf * 2]     = p0;
                    s[mt][nt][hf * 2 + 1] = p1;
                }
                rsum += __shfl_xor_sync(0xffffffffu, rsum, 1);
                rsum += __shfl_xor_sync(0xffffffffu, rsum, 2);
                m[mt][hf] = mnew;
                l[mt][hf] = l[mt][hf] * al + rsum;
#pragma unroll
                for (int nt = 0; nt < 8; nt++) {
                    o[mt][nt][hf * 2]     *= al;
                    o[mt][nt][hf * 2 + 1] *= al;
                }
            }
        }

        unsigned pf[2][4][4];
#pragma unroll
        for (int mt = 0; mt < 2; mt++)
#pragma unroll
            for (int j = 0; j < 4; j++) {
                __half2 h0 = __floats2half2_rn(s[mt][2*j][0],   s[mt][2*j][1]);
                __half2 h1 = __floats2half2_rn(s[mt][2*j][2],   s[mt][2*j][3]);
                __half2 h2 = __floats2half2_rn(s[mt][2*j+1][0], s[mt][2*j+1][1]);
                __half2 h3 = __floats2half2_rn(s[mt][2*j+1][2], s[mt][2*j+1][3]);
                pf[mt][j][0] = *(unsigned*)&h0;
                pf[mt][j][1] = *(unsigned*)&h1;
                pf[mt][j][2] = *(unsigned*)&h2;
                pf[mt][j][3] = *(unsigned*)&h3;
            }

#pragma unroll
        for (int j = 0; j < 4; j++) {
            unsigned bf[8][2];
#pragma unroll
            for (int nt = 0; nt < 8; nt++) {
                unsigned bd = vsbase +
                    (unsigned)((j * 16 + b_lr) * HSTR + nt * 8) * 2u;
                asm volatile(
                    "ldmatrix.sync.aligned.m8n8.x2.trans.shared.b16 "
                    "{%0,%1}, [%2];"
                    : "=r"(bf[nt][0]), "=r"(bf[nt][1]) : "r"(bd));
            }
#pragma unroll
            for (int mt = 0; mt < 2; mt++)
#pragma unroll
                for (int nt = 0; nt < 8; nt++)
                    mma_f16(o[mt][nt], pf[mt][j], bf[nt]);
        }
    }

#pragma unroll
    for (int mt = 0; mt < 2; mt++) {
#pragma unroll
        for (int hf = 0; hf < 2; hf++) {
            int rloc = warp * 32 + mt * 16 + g + hf * 8;
            float invl = 1.f / l[mt][hf];
            size_t ob = ((size_t)(b * T_ + qb * QT + rloc)) * DIM_ + h * HD_;
#pragma unroll
            for (int nt = 0; nt < 8; nt++) {
                int c = nt * 8 + t * 2;
                *(__half2*)(out + ob + c) = __floats2half2_rn(
                    o[mt][nt][hf * 2]     * invl,
                    o[mt][nt][hf * 2 + 1] * invl);
            }
        }
    }
}

// ---------------------------------------------------------------------------
extern "C" void kernel_launch(void* const* d_in, const int* in_sizes, int n_in,
                              void* d_out, int out_size)
{
    const float* x     = (const float*)d_in[0];
    const int*   kpm   = (const int*)  d_in[1];
    const float* ln1w  = (const float*)d_in[2];
    const float* ln1b  = (const float*)d_in[3];
    const float* qkvw  = (const float*)d_in[4];
    const float* projw = (const float*)d_in[5];
    const float* projb = (const float*)d_in[6];
    const float* ln2w  = (const float*)d_in[7];
    const float* ln2b  = (const float*)d_in[8];
    const float* fc1w  = (const float*)d_in[9];
    const float* fc1b  = (const float*)d_in[10];
    const float* fc2w  = (const float*)d_in[11];
    const float* fc2b  = (const float*)d_in[12];
    float* out = (float*)d_out;

    __half *h1, *qkv, *att, *h2, *f1, *wq, *wp, *w1, *w2;
    float *x2;
    cudaGetSymbolAddress((void**)&h1,  g_h1);
    cudaGetSymbolAddress((void**)&qkv, g_qkv);
    cudaGetSymbolAddress((void**)&att, g_att);
    cudaGetSymbolAddress((void**)&x2,  g_x2);
    cudaGetSymbolAddress((void**)&h2,  g_h2);
    cudaGetSymbolAddress((void**)&f1,  g_f1);
    cudaGetSymbolAddress((void**)&wq,  g_wq);
    cudaGetSymbolAddress((void**)&wp,  g_wp);
    cudaGetSymbolAddress((void**)&w1,  g_w1);
    cudaGetSymbolAddress((void**)&w2,  g_w2);

    cudaFuncSetAttribute(attn_f16,
        cudaFuncAttributeMaxDynamicSharedMemorySize, ATTN_SMEM);
    cudaFuncSetAttribute(gemm_f16<0>,
        cudaFuncAttributeMaxDynamicSharedMemorySize, GEMM_SMEM);
    cudaFuncSetAttribute(gemm_f16<1>,
        cudaFuncAttributeMaxDynamicSharedMemorySize, GEMM_SMEM);
    cudaFuncSetAttribute(gemm_f16<2>,
        cudaFuncAttributeMaxDynamicSharedMemorySize, GEMM_SMEM);

    // 0) fused prologue: LN1 + all weight conversions in ONE launch
    prep_kernel<<<NTOK + CONV_BLOCKS, 256>>>(
        x, ln1w, ln1b, h1, qkvw, projw, fc1w, fc2w, wq, wp, w1, w2);

    // 2) QKV GEMM (fp16 out)
    gemm_f16<0><<<dim3(3*DIM_/BN, NTOK/BM), 128, GEMM_SMEM>>>(
        h1, wq, nullptr, nullptr, qkv, NTOK, 3*DIM_, DIM_);
    // 3) Attention (fp16 in/out)
    attn_f16<<<dim3(T_/QT, NH_, B_), 128, ATTN_SMEM>>>(qkv, kpm, att);
    // 4) proj GEMM + bias + residual(x) -> x2 (float)
    gemm_f16<1><<<dim3(DIM_/BN, NTOK/BM), 128, GEMM_SMEM>>>(
        att, wp, projb, x, x2, NTOK, DIM_, DIM_);
    // 5) LN2 (fp16 out)
    ln_kernel<<<NTOK, 256>>>(x2, ln2w, ln2b, h2);
    // 6) fc1 GEMM + bias + GELU -> f1 (fp16)
    gemm_f16<2><<<dim3(HID_/BN, NTOK/BM), 128, GEMM_SMEM>>>(
        h2, w1, fc1b, nullptr, f1, NTOK, HID_, DIM_);
    // 7) fc2 GEMM + bias + residual(x2) -> out (float)
    gemm_f16<1><<<dim3(DIM_/BN, NTOK/BM), 128, GEMM_SMEM>>>(
        f1, w2, fc2b, x2, out, NTOK, DIM_, HID_);
}